// round 2
// baseline (speedup 1.0000x reference)
#include <cuda_runtime.h>
#include <math.h>

#define Bn 512
#define Tn 512
#define Hn 512
#define GT 32          // hidden-slice tiles
#define BT 4           // batch tiles
#define JS 16          // hidden units per block  (Hn/GT)
#define BS 128         // batch rows per block    (Bn/BT)
#define NBLK (GT*BT)   // 128 blocks, all co-resident on 148 SMs
#define NTHR 512
#define W_STRIDE 68    // 64 gate-cols padded; k-row stride (floats)
#define H_STRIDE 132   // 128 batch padded; k-row stride (floats)

// Scratch (no cudaMalloc allowed): h ping-pong stored TRANSPOSED [hidden][batch]
__device__ float g_h[2][Hn][Bn];
__device__ float g_seqT[Tn][Bn];
__device__ unsigned g_count = 0;
__device__ volatile unsigned g_gen = 0;

__device__ __forceinline__ void grid_sync(unsigned target) {
    __syncthreads();
    if (threadIdx.x == 0) {
        __threadfence();
        unsigned old = atomicAdd(&g_count, 1u);
        if (old == NBLK - 1) {
            g_count = 0;          // reset for next barrier
            __threadfence();
            g_gen = target;       // release (volatile store)
        } else {
            while (g_gen != target) { }
            __threadfence();      // acquire
        }
    }
    __syncthreads();
}

__device__ __forceinline__ float sigf(float x) { return 1.0f / (1.0f + expf(-x)); }

__global__ __launch_bounds__(NTHR, 1)
void lstm_persistent(const float* __restrict__ seq,
                     const float* __restrict__ Wih,
                     const float* __restrict__ Whh,
                     const float* __restrict__ bih,
                     const float* __restrict__ bhh)
{
    extern __shared__ float smem[];
    float* w_s    = smem;                      // [512][W_STRIDE] : W_hh slice, layout [k][jl*4+g]
    float* h_s    = w_s + 512 * W_STRIDE;      // [64][H_STRIDE]  : h chunk, layout [k][b]
    float* wih_s  = h_s + 64 * H_STRIDE;       // [64] : [jl*4+g]
    float* bias_s = wih_s + 64;                // [64] : b_ih + b_hh folded
    __shared__ unsigned s_base;

    const int tid = threadIdx.x;
    const int tx  = tid & 15;    // local hidden unit j
    const int ty  = tid >> 4;    // batch group (0..31), owns 4 rows
    const int bi  = blockIdx.x >> 5;   // 0..3
    const int ji  = blockIdx.x & 31;   // 0..31
    const int b0  = bi * BS;
    const int j0  = ji * JS;

    if (tid == 0) s_base = g_gen;  // stable: no block can bump g_gen before all arrive at barrier 0

    // Load W_hh slice into SMEM once; kept resident for all 512 steps.
    for (int idx = tid; idx < 64 * 512; idx += NTHR) {
        int rr = idx >> 9;          // 0..63 = g*16 + jl
        int k  = idx & 511;
        int g  = rr >> 4;
        int jl = rr & 15;
        w_s[k * W_STRIDE + jl * 4 + g] = Whh[(size_t)(g * Hn + j0 + jl) * Hn + k];
    }
    if (tid < 64) {
        int jl = tid >> 2, g = tid & 3;
        int row = g * Hn + j0 + jl;
        wih_s[jl * 4 + g]  = Wih[row];
        bias_s[jl * 4 + g] = bih[row] + bhh[row];
    }

    // Zero h0 (buffer 0) and transpose sequence -> g_seqT[t][b] (coalesced reads)
    {
        float* h0p = &g_h[0][0][0];
        int base = blockIdx.x * 2048;
        #pragma unroll
        for (int i = 0; i < 4; ++i) {
            int idx = base + i * NTHR + tid;
            h0p[idx] = 0.0f;
            int b = idx >> 9, t = idx & 511;
            g_seqT[t][b] = seq[idx];           // seq is [b][t][1]
        }
    }
    grid_sync(s_base + 1);
    const unsigned base_gen = s_base;

    float c0 = 0.f, c1 = 0.f, c2 = 0.f, c3 = 0.f;   // cell state lives in registers

    for (int t = 0; t < Tn; ++t) {
        const float* hbuf = &g_h[t & 1][0][0];
        float* hout       = &g_h[(t & 1) ^ 1][0][0];

        float4 sv = *(const float4*)&g_seqT[t][b0 + ty * 4];
        float4 wi = *(const float4*)&wih_s[tx * 4];
        float4 bb = *(const float4*)&bias_s[tx * 4];

        // acc[r][g]: r = batch row in group, g = gate (i,f,g,o)
        float a00 = fmaf(sv.x, wi.x, bb.x), a01 = fmaf(sv.x, wi.y, bb.y),
              a02 = fmaf(sv.x, wi.z, bb.z), a03 = fmaf(sv.x, wi.w, bb.w);
        float a10 = fmaf(sv.y, wi.x, bb.x), a11 = fmaf(sv.y, wi.y, bb.y),
              a12 = fmaf(sv.y, wi.z, bb.z), a13 = fmaf(sv.y, wi.w, bb.w);
        float a20 = fmaf(sv.z, wi.x, bb.x), a21 = fmaf(sv.z, wi.y, bb.y),
              a22 = fmaf(sv.z, wi.z, bb.z), a23 = fmaf(sv.z, wi.w, bb.w);
        float a30 = fmaf(sv.w, wi.x, bb.x), a31 = fmaf(sv.w, wi.y, bb.y),
              a32 = fmaf(sv.w, wi.z, bb.z), a33 = fmaf(sv.w, wi.w, bb.w);

        #pragma unroll 1
        for (int kc = 0; kc < 8; ++kc) {
            __syncthreads();
            // Stage h chunk [64 k][128 b]; reads coalesced, SMEM writes conflict-free
            #pragma unroll
            for (int i = 0; i < 16; ++i) {
                int idx = i * NTHR + tid;
                int k = idx >> 7, b = idx & 127;
                h_s[k * H_STRIDE + b] = hbuf[(size_t)(kc * 64 + k) * Bn + b0 + b];
            }
            __syncthreads();

            const float* wp = w_s + (kc * 64) * W_STRIDE + tx * 4;
            const float* hp = h_s + ty * 4;
            #pragma unroll 8
            for (int k = 0; k < 64; ++k) {
                float4 w  = *(const float4*)(wp + k * W_STRIDE);
                float4 hv = *(const float4*)(hp + k * H_STRIDE);
                a00 = fmaf(hv.x, w.x, a00); a01 = fmaf(hv.x, w.y, a01);
                a02 = fmaf(hv.x, w.z, a02); a03 = fmaf(hv.x, w.w, a03);
                a10 = fmaf(hv.y, w.x, a10); a11 = fmaf(hv.y, w.y, a11);
                a12 = fmaf(hv.y, w.z, a12); a13 = fmaf(hv.y, w.w, a13);
                a20 = fmaf(hv.z, w.x, a20); a21 = fmaf(hv.z, w.y, a21);
                a22 = fmaf(hv.z, w.z, a22); a23 = fmaf(hv.z, w.w, a23);
                a30 = fmaf(hv.w, w.x, a30); a31 = fmaf(hv.w, w.y, a31);
                a32 = fmaf(hv.w, w.z, a32); a33 = fmaf(hv.w, w.w, a33);
            }
        }

        // LSTM cell (PyTorch gate order i,f,g,o)
        c0 = sigf(a01) * c0 + sigf(a00) * tanhf(a02);
        c1 = sigf(a11) * c1 + sigf(a10) * tanhf(a12);
        c2 = sigf(a21) * c2 + sigf(a20) * tanhf(a22);
        c3 = sigf(a31) * c3 + sigf(a30) * tanhf(a32);
        float4 ho;
        ho.x = sigf(a03) * tanhf(c0);
        ho.y = sigf(a13) * tanhf(c1);
        ho.z = sigf(a23) * tanhf(c2);
        ho.w = sigf(a33) * tanhf(c3);
        *(float4*)&hout[(size_t)(j0 + tx) * Bn + b0 + ty * 4] = ho;

        grid_sync(base_gen + 2 + t);
    }
    // Final h (t=511 writes buffer 0) consumed by mlp_head.
}

__global__ __launch_bounds__(256)
void mlp_head(const float* __restrict__ fc1w, const float* __restrict__ fc1b,
              const float* __restrict__ fc2w, const float* __restrict__ fc2b,
              float* __restrict__ out)
{
    __shared__ float hcol[512];
    __shared__ float z[256];
    const int b = blockIdx.x;
    const int tid = threadIdx.x;

    hcol[tid]       = g_h[0][tid][b];
    hcol[tid + 256] = g_h[0][tid + 256][b];
    __syncthreads();

    float acc = fc1b[tid];
    const float4* w4 = (const float4*)(fc1w + (size_t)tid * 512);
    const float4* h4 = (const float4*)hcol;
    #pragma unroll 4
    for (int k = 0; k < 128; ++k) {
        float4 w = w4[k], h = h4[k];
        acc = fmaf(w.x, h.x, acc); acc = fmaf(w.y, h.y, acc);
        acc = fmaf(w.z, h.z, acc); acc = fmaf(w.w, h.w, acc);
    }
    z[tid] = fmaxf(acc, 0.0f);
    __syncthreads();

    if (tid < 28) {
        float o = fc2b[tid];
        const float4* w4b = (const float4*)(fc2w + (size_t)tid * 256);
        const float4* z4  = (const float4*)z;
        #pragma unroll 4
        for (int k = 0; k < 64; ++k) {
            float4 w = w4b[k], zz = z4[k];
            o = fmaf(w.x, zz.x, o); o = fmaf(w.y, zz.y, o);
            o = fmaf(w.z, zz.z, o); o = fmaf(w.w, zz.w, o);
        }
        out[b * 28 + tid] = o;
    }
}

extern "C" void kernel_launch(void* const* d_in, const int* in_sizes, int n_in,
                              void* d_out, int out_size) {
    const float* seq  = (const float*)d_in[0];
    const float* Wih  = (const float*)d_in[1];
    const float* Whh  = (const float*)d_in[2];
    const float* bih  = (const float*)d_in[3];
    const float* bhh  = (const float*)d_in[4];
    const float* fc1w = (const float*)d_in[5];
    const float* fc1b = (const float*)d_in[6];
    const float* fc2w = (const float*)d_in[7];
    const float* fc2b = (const float*)d_in[8];
    float* out = (float*)d_out;

    size_t smem_bytes = (size_t)(512 * W_STRIDE + 64 * H_STRIDE + 128) * sizeof(float);
    cudaFuncSetAttribute(lstm_persistent, cudaFuncAttributeMaxDynamicSharedMemorySize,
                         (int)smem_bytes);

    lstm_persistent<<<NBLK, NTHR, smem_bytes>>>(seq, Wih, Whh, bih, bhh);
    mlp_head<<<Bn, 256>>>(fc1w, fc1b, fc2w, fc2b, out);
}